// round 14
// baseline (speedup 1.0000x reference)
#include <cuda_runtime.h>
#include <cuda_fp16.h>
#include <math.h>
#include <stdint.h>

// Problem constants
#define BDIM   2
#define SLEN   2048
#define DMODEL 2048
#define NH     16
#define HD     128
#define MROWS  (BDIM * SLEN)   // 4096
#define NQKV   2304

// ---------------- scratch (no allocations allowed) ----------------
__device__ __half g_xh[(size_t)MROWS * DMODEL];
__device__ __half g_wh[(size_t)NQKV * DMODEL];   // [0,2048)=Wq [2048,2176)=Wk [2176,2304)=Wv
__device__ __half g_woh[(size_t)DMODEL * DMODEL];
__device__ __half g_qh[(size_t)MROWS * DMODEL];
__device__ __half g_kh[(size_t)MROWS * HD];
__device__ __half g_vth[(size_t)BDIM * HD * SLEN];   // [b][j][s]
__device__ __half g_ah[(size_t)MROWS * DMODEL];      // attn out, flat (b,h,s,hd)

// ---------------- helpers ----------------
__device__ __forceinline__ uint32_t smem_u32(const void* p) {
    uint32_t a;
    asm("{ .reg .u64 t; cvta.to.shared.u64 t, %1; cvt.u32.u64 %0, t; }" : "=r"(a) : "l"(p));
    return a;
}
#define CP16(dst, src) \
    asm volatile("cp.async.cg.shared.global [%0], [%1], 16;" :: "r"(dst), "l"(src) : "memory")
#define CPCOMMIT() asm volatile("cp.async.commit_group;" ::: "memory")
#define CPWAIT(n)  asm volatile("cp.async.wait_group %0;" :: "n"(n) : "memory")
#define LDSM4(r0, r1, r2, r3, addr) \
    asm volatile("ldmatrix.sync.aligned.m8n8.x4.shared.b16 {%0,%1,%2,%3},[%4];" \
        : "=r"(r0), "=r"(r1), "=r"(r2), "=r"(r3) : "r"(addr))

__device__ __forceinline__ void mma16816(float c[4],
    uint32_t a0, uint32_t a1, uint32_t a2, uint32_t a3, uint32_t b0, uint32_t b1)
{
    asm volatile(
        "mma.sync.aligned.m16n8k16.row.col.f32.f16.f16.f32 "
        "{%0,%1,%2,%3},{%4,%5,%6,%7},{%8,%9},{%0,%1,%2,%3};"
        : "+f"(c[0]), "+f"(c[1]), "+f"(c[2]), "+f"(c[3])
        : "r"(a0), "r"(a1), "r"(a2), "r"(a3), "r"(b0), "r"(b1));
}

// f16-accumulate variant
__device__ __forceinline__ void mma16816h(uint32_t c[2],
    uint32_t a0, uint32_t a1, uint32_t a2, uint32_t a3, uint32_t b0, uint32_t b1)
{
    asm volatile(
        "mma.sync.aligned.m16n8k16.row.col.f16.f16.f16.f16 "
        "{%0,%1},{%2,%3,%4,%5},{%6,%7},{%0,%1};"
        : "+r"(c[0]), "+r"(c[1])
        : "r"(a0), "r"(a1), "r"(a2), "r"(a3), "r"(b0), "r"(b1));
}

__device__ __forceinline__ uint32_t packh(float x, float y) {
    __half2 t = __floats2half2_rn(x, y);
    return reinterpret_cast<uint32_t&>(t);
}
__device__ __forceinline__ uint32_t ex2h2(uint32_t x) {
    uint32_t r;
    asm("ex2.approx.f16x2 %0, %1;" : "=r"(r) : "r"(x));
    return r;
}
__device__ __forceinline__ uint32_t hmul2(uint32_t a, uint32_t b) {
    __half2 r = __hmul2(reinterpret_cast<__half2&>(a), reinterpret_cast<__half2&>(b));
    return reinterpret_cast<uint32_t&>(r);
}
__device__ __forceinline__ uint32_t hadd2(uint32_t a, uint32_t b) {
    __half2 r = __hadd2(reinterpret_cast<__half2&>(a), reinterpret_cast<__half2&>(b));
    return reinterpret_cast<uint32_t&>(r);
}

// ---------------- fp32 -> fp16 conversions ----------------
// main: x + qkv weights (needed before qkv); wo: converted concurrently on a side stream
#define C_X    2097152   // 4096*2048/4
#define C_WQ   1048576   // 2048*2048/4
#define C_WKV  65536     // 128*2048/4
#define C_MAIN (C_X + C_WQ + 2 * C_WKV)   // 3276800
#define C_WO   1048576

__global__ __launch_bounds__(256) void cvt_main_kernel(
    const float* __restrict__ x,  const float* __restrict__ Wq,
    const float* __restrict__ Wk, const float* __restrict__ Wv)
{
    int i = blockIdx.x * blockDim.x + threadIdx.x;
    if (i >= C_MAIN) return;
    const float* src; __half* dst; int off;
    if (i < C_X)                          { src = x;  dst = g_xh;  off = i; }
    else if (i < C_X + C_WQ)              { src = Wq; dst = g_wh;  off = i - C_X; }
    else if (i < C_X + C_WQ + C_WKV)      { src = Wk; dst = g_wh + (size_t)2048 * DMODEL; off = i - (C_X + C_WQ); }
    else                                  { src = Wv; dst = g_wh + (size_t)2176 * DMODEL; off = i - (C_X + C_WQ + C_WKV); }
    float4 v = ((const float4*)src)[off];
    uint2 H;
    H.x = packh(v.x, v.y);
    H.y = packh(v.z, v.w);
    ((uint2*)dst)[off] = H;
}

__global__ __launch_bounds__(256) void cvt_wo_kernel(const float* __restrict__ Wo)
{
    int i = blockIdx.x * blockDim.x + threadIdx.x;
    if (i >= C_WO) return;
    float4 v = ((const float4*)Wo)[i];
    uint2 H;
    H.x = packh(v.x, v.y);
    H.y = packh(v.z, v.w);
    ((uint2*)g_woh)[i] = H;
}

// ---------------- GEMM core: 128x128 block, K=2048, 3-stage pipeline ----------------
#define GSTR 72
#define GT   (128 * GSTR)          // 9216 elems per tensor tile
#define GSTAGE (2 * GT)            // A, B per stage
#define GNST 3
#define GEMM_SMEM (GNST * GSTAGE * 2)   // 110592 bytes
#define NCHUNK (DMODEL / 64)            // 32

__device__ __forceinline__ void gemm_core(
    const __half* __restrict__ A, const __half* __restrict__ B,
    float acc[2][8][4])
{
    extern __shared__ __align__(16) __half smg[];
    const uint32_t sb = smem_u32(smg);
    const int tid = threadIdx.x, lane = tid & 31, wid = tid >> 5;
    const int wm = wid & 3, wn = wid >> 2;

#pragma unroll
    for (int mt = 0; mt < 2; mt++)
#pragma unroll
        for (int nt = 0; nt < 8; nt++)
#pragma unroll
            for (int j = 0; j < 4; j++) acc[mt][nt][j] = 0.f;

    const int la = lane & 15, lb = lane >> 4;                 // A x4
    const int ln = (lane & 7) + ((lane >> 4) << 3);           // B x4 row
    const int lk = (lane >> 3) & 1;                           // B x4 k-half

    auto issue = [&](int c, int st) {
        const size_t k0 = (size_t)c * 64;
        const uint32_t dA = sb + (uint32_t)(st * GSTAGE) * 2;
        const uint32_t dB = dA + (uint32_t)GT * 2;
#pragma unroll
        for (int j = 0; j < 4; j++) {
            int idx = tid + j * 256;           // 0..1023
            int row = idx >> 3, slot = idx & 7;
            uint32_t doff = (uint32_t)(row * GSTR + slot * 8) * 2;
            size_t go = (size_t)row * DMODEL + k0 + slot * 8;
            CP16(dA + doff, A + go);
            CP16(dB + doff, B + go);
        }
        CPCOMMIT();
    };

    issue(0, 0);
    issue(1, 1);
    for (int c = 0; c < NCHUNK; c++) {
        const int st = c % GNST;
        if (c + 1 < NCHUNK) { CPWAIT(1); }
        else                { CPWAIT(0); }
        __syncthreads();
        if (c + 2 < NCHUNK) issue(c + 2, (c + 2) % GNST);

        const uint32_t A0 = sb + (uint32_t)(st * GSTAGE) * 2;
        const uint32_t B0 = A0 + (uint32_t)GT * 2;

#pragma unroll
        for (int ks = 0; ks < 4; ks++) {
            uint32_t aH[2][4];
#pragma unroll
            for (int mt = 0; mt < 2; mt++) {
                uint32_t ra = (uint32_t)((32 * wm + 16 * mt + la) * GSTR + ks * 16) * 2 + lb * 16;
                LDSM4(aH[mt][0], aH[mt][1], aH[mt][2], aH[mt][3], A0 + ra);
            }
#pragma unroll
            for (int ntp = 0; ntp < 4; ntp++) {
                uint32_t rb = (uint32_t)((64 * wn + 16 * ntp + ln) * GSTR + ks * 16) * 2 + lk * 16;
                uint32_t bh0, bh1, bh2, bh3;
                LDSM4(bh0, bh1, bh2, bh3, B0 + rb);
#pragma unroll
                for (int mt = 0; mt < 2; mt++) {
                    mma16816(acc[mt][2 * ntp],     aH[mt][0], aH[mt][1], aH[mt][2], aH[mt][3], bh0, bh1);
                    mma16816(acc[mt][2 * ntp + 1], aH[mt][0], aH[mt][1], aH[mt][2], aH[mt][3], bh2, bh3);
                }
            }
        }
    }
}

// ---------------- QKV projection ----------------
__global__ __launch_bounds__(256, 2) void qkv_mma_kernel(
    const float* __restrict__ bq, const float* __restrict__ bk, const float* __restrict__ bv)
{
    const int bn = blockIdx.x;   // 0..17
    const int bm = blockIdx.y;   // 0..31
    const int m0 = bm * 128;

    const __half* Bh;
    const float* bias;
    if (bn < 16)       { Bh = g_wh + (size_t)bn * 128 * DMODEL; bias = bq + bn * 128; }
    else if (bn == 16) { Bh = g_wh + (size_t)2048 * DMODEL;     bias = bk; }
    else               { Bh = g_wh + (size_t)2176 * DMODEL;     bias = bv; }

    float acc[2][8][4];
    gemm_core(g_xh + (size_t)m0 * DMODEL, Bh, acc);

    const int lane = threadIdx.x & 31, wid = threadIdx.x >> 5;
    const int wm = wid & 3, wn = wid >> 2;
    const int gr = lane >> 2, q4 = lane & 3;

#pragma unroll
    for (int mt = 0; mt < 2; mt++) {
#pragma unroll
        for (int nt = 0; nt < 8; nt++) {
            int rl = 32 * wm + 16 * mt + gr;
            int cl = 64 * wn + 8 * nt + 2 * q4;
            float bb0 = bias[cl], bb1 = bias[cl + 1];
#pragma unroll
            for (int hf = 0; hf < 2; hf++) {
                int r = rl + 8 * hf;
                float v0 = acc[mt][nt][2 * hf] + bb0;
                float v1 = acc[mt][nt][2 * hf + 1] + bb1;
                if (bn < 16) {
                    *(uint32_t*)&g_qh[(size_t)(m0 + r) * DMODEL + bn * 128 + cl] = packh(v0, v1);
                } else if (bn == 16) {
                    *(uint32_t*)&g_kh[(size_t)(m0 + r) * HD + cl] = packh(v0, v1);
                } else {
                    int mg = m0 + r;
                    int b = mg >> 11, s = mg & 2047;
                    size_t o0 = (size_t)b * HD * SLEN + (size_t)cl * SLEN + s;
                    g_vth[o0]        = __float2half_rn(v0);
                    g_vth[o0 + SLEN] = __float2half_rn(v1);
                }
            }
        }
    }
}

// ---------------- output projection ----------------
__global__ __launch_bounds__(256, 2) void oproj_mma_kernel(const float* __restrict__ bo,
                                                           float* __restrict__ out)
{
    const int bn = blockIdx.x;   // 0..15
    const int bm = blockIdx.y;   // 0..31
    const int m0 = bm * 128;
    const int n0 = bn * 128;

    float acc[2][8][4];
    gemm_core(g_ah + (size_t)m0 * DMODEL, g_woh + (size_t)n0 * DMODEL, acc);

    const int lane = threadIdx.x & 31, wid = threadIdx.x >> 5;
    const int wm = wid & 3, wn = wid >> 2;
    const int gr = lane >> 2, q4 = lane & 3;

#pragma unroll
    for (int mt = 0; mt < 2; mt++) {
#pragma unroll
        for (int nt = 0; nt < 8; nt++) {
            int rl = 32 * wm + 16 * mt + gr;
            int cl = 64 * wn + 8 * nt + 2 * q4;
            float bb0 = bo[n0 + cl], bb1 = bo[n0 + cl + 1];
#pragma unroll
            for (int hf = 0; hf < 2; hf++) {
                int r = rl + 8 * hf;
                float2 o2;
                o2.x = acc[mt][nt][2 * hf] + bb0;
                o2.y = acc[mt][nt][2 * hf + 1] + bb1;
                *(float2*)&out[(size_t)(m0 + r) * DMODEL + n0 + cl] = o2;
            }
        }
    }
}

// ---------------- attention (fp16 S-path; Q via cp.async; exp/PV interleaved) ----------------
#define QSTR 136
#define KSTR 136
#define VSTR 72
#define AQ_ELEMS (128 * QSTR)              // 17408
#define AK_ELEMS (64 * KSTR)               // 8704
#define AV_ELEMS (128 * VSTR)              // 9216
#define ASTAGE   (AK_ELEMS + AV_ELEMS)     // 17920 elems
#define OFF_ST   AQ_ELEMS
#define ATT_SMEM ((AQ_ELEMS + 2 * ASTAGE) * 2)   // 106496 bytes
#define NKT (SLEN / 64)                    // 32

__global__ __launch_bounds__(256, 2) void attn_mma_kernel()
{
    extern __shared__ __align__(16) __half sm[];
    const uint32_t sb = smem_u32(sm);
    const int tid = threadIdx.x, lane = tid & 31, w = tid >> 5;
    const int qt = blockIdx.x, h = blockIdx.y, b = blockIdx.z;
    const int q0 = qt * 128;
    const int gr = lane >> 2, q4 = lane & 3;

    const __half* kbH = g_kh + (size_t)b * SLEN * HD;
    const __half* vbH = g_vth + (size_t)b * HD * SLEN;

    auto issue_kv = [&](int kt, int st) {
        const uint32_t stb = sb + (uint32_t)(OFF_ST + st * ASTAGE) * 2;
        const __half* kh = kbH + (size_t)kt * 64 * HD;
#pragma unroll
        for (int j = 0; j < 4; j++) {
            int idx = tid + j * 256;
            int row = idx >> 4, slot = idx & 15;
            CP16(stb + (uint32_t)(row * KSTR + slot * 8) * 2,
                 kh + (size_t)row * HD + slot * 8);
        }
        const __half* vh = vbH + (size_t)kt * 64;
#pragma unroll
        for (int j = 0; j < 4; j++) {
            int idx = tid + j * 256;
            int row = idx >> 3, slot = idx & 7;
            CP16(stb + (uint32_t)AK_ELEMS * 2 + (uint32_t)(row * VSTR + slot * 8) * 2,
                 vh + (size_t)row * SLEN + slot * 8);
        }
        CPCOMMIT();
    };

    // Q tile (128 x 128) via cp.async, issued first; lands with KV0 at iter-0 wait
    {
        const __half* qsH = g_qh + ((size_t)(b * SLEN + q0)) * DMODEL + h * HD;
#pragma unroll
        for (int it = 0; it < 8; it++) {
            int idx = tid + it * 256;
            int row = idx >> 4, slot = idx & 15;
            CP16(sb + (uint32_t)(row * QSTR + slot * 8) * 2,
                 qsH + (size_t)row * DMODEL + slot * 8);
        }
        CPCOMMIT();
    }
    issue_kv(0, 0);

    float oacc[16][4];
#pragma unroll
    for (int nt = 0; nt < 16; nt++)
#pragma unroll
        for (int j = 0; j < 4; j++) oacc[nt][j] = 0.f;

    float acc0 = 0.f, acc1 = 0.f;
    const uint32_t C2H = packh(0.12751744f, 0.12751744f);   // log2(e)/sqrt(128)
    const int qrow = 16 * w;

    const int la = lane & 15, lb = lane >> 4;
    const int ln = (lane & 7) + ((lane >> 4) << 3);
    const int lk = (lane >> 3) & 1;

    for (int kt = 0; kt < NKT; kt++) {
        const int st = kt & 1;
        CPWAIT(0);
        __syncthreads();
        if (kt + 1 < NKT) issue_kv(kt + 1, st ^ 1);   // overlaps all compute below

        const uint32_t stb = sb + (uint32_t)(OFF_ST + st * ASTAGE) * 2;
        const uint32_t KH0 = stb;
        const uint32_t VH0 = stb + (uint32_t)AK_ELEMS * 2;

        // S = Q @ K^T in f16-accumulate
        uint32_t sD[8][2];
#pragma unroll
        for (int nt = 0; nt < 8; nt++) { sD[nt][0] = 0u; sD[nt][1] = 0u; }

#pragma unroll
        for (int ks = 0; ks < 8; ks++) {
            uint32_t ra = (uint32_t)((qrow + la) * QSTR + ks * 16) * 2 + lb * 16;
            uint32_t aH0, aH1, aH2, aH3;
            LDSM4(aH0, aH1, aH2, aH3, sb + ra);
#pragma unroll
            for (int ntp = 0; ntp < 4; ntp++) {
                uint32_t rb = (uint32_t)((16 * ntp + ln) * KSTR + ks * 16) * 2 + lk * 16;
                uint32_t bh0, bh1, bh2, bh3;
                LDSM4(bh0, bh1, bh2, bh3, KH0 + rb);
                mma16816h(sD[2 * ntp],     aH0, aH1, aH2, aH3, bh0, bh1);
                mma16816h(sD[2 * ntp + 1], aH0, aH1, aH2, aH3, bh2, bh3);
            }
        }

        // exp interleaved with PV per kc-slice
        uint32_t d0 = 0u, d1 = 0u;
#pragma unroll
        for (int kc = 0; kc < 4; kc++) {
            uint32_t pa0 = ex2h2(hmul2(sD[2 * kc][0],     C2H));
            uint32_t pa1 = ex2h2(hmul2(sD[2 * kc][1],     C2H));
            uint32_t pb0 = ex2h2(hmul2(sD[2 * kc + 1][0], C2H));
            uint32_t pb1 = ex2h2(hmul2(sD[2 * kc + 1][1], C2H));
            d0 = hadd2(d0, hadd2(pa0, pb0));
            d1 = hadd2(d1, hadd2(pa1, pb1));
#pragma unroll
            for (int ntp = 0; ntp < 8; ntp++) {
                uint32_t rb = (uint32_t)((16 * ntp + ln) * VSTR + kc * 16) * 2 + lk * 16;
                uint32_t bh0, bh1, bh2, bh3;
                LDSM4(bh0, bh1, bh2, bh3, VH0 + rb);
                mma16816(oacc[2 * ntp],     pa0, pa1, pb0, pb1, bh0, bh1);
                mma16816(oacc[2 * ntp + 1], pa0, pa1, pb0, pb1, bh2, bh3);
            }
        }
        {
            float2 f0 = __half22float2(reinterpret_cast<__half2&>(d0));
            float2 f1 = __half22float2(reinterpret_cast<__half2&>(d1));
            acc0 += f0.x + f0.y;
            acc1 += f1.x + f1.y;
        }
    }

    // final denominator reduction across the quad (lanes sharing a row)
    acc0 += __shfl_xor_sync(0xffffffffu, acc0, 1);
    acc0 += __shfl_xor_sync(0xffffffffu, acc0, 2);
    acc1 += __shfl_xor_sync(0xffffffffu, acc1, 1);
    acc1 += __shfl_xor_sync(0xffffffffu, acc1, 2);
    float i0 = 1.f / acc0, i1 = 1.f / acc1;

    // normalize + write fp16 to flat (b,h,s,hd)
    size_t rg = (size_t)((b * NH + h) * SLEN + q0 + qrow + gr);
#pragma unroll
    for (int nt = 0; nt < 16; nt++) {
        int col = 8 * nt + 2 * q4;
        *(uint32_t*)&g_ah[rg * HD + col]       = packh(oacc[nt][0] * i0, oacc[nt][1] * i0);
        *(uint32_t*)&g_ah[(rg + 8) * HD + col] = packh(oacc[nt][2] * i1, oacc[nt][3] * i1);
    }
}

// ---------------- launch ----------------
extern "C" void kernel_launch(void* const* d_in, const int* in_sizes, int n_in,
                              void* d_out, int out_size)
{
    const float* x  = (const float*)d_in[0];
    const float* Wq = (const float*)d_in[1];
    const float* bq = (const float*)d_in[2];
    const float* Wk = (const float*)d_in[3];
    const float* bk = (const float*)d_in[4];
    const float* Wv = (const float*)d_in[5];
    const float* bv = (const float*)d_in[6];
    const float* Wo = (const float*)d_in[7];
    const float* bo = (const float*)d_in[8];
    float* out = (float*)d_out;

    cudaFuncSetAttribute(qkv_mma_kernel,   cudaFuncAttributeMaxDynamicSharedMemorySize, GEMM_SMEM);
    cudaFuncSetAttribute(oproj_mma_kernel, cudaFuncAttributeMaxDynamicSharedMemorySize, GEMM_SMEM);
    cudaFuncSetAttribute(attn_mma_kernel,  cudaFuncAttributeMaxDynamicSharedMemorySize, ATT_SMEM);

    // Side stream for the Wo conversion: it has no consumers until oproj, so it
    // runs concurrently with cvt_main + qkv + attention. Handles are created once
    // (host-side; no device allocation) and intentionally never destroyed —
    // kernel_launch only runs for the correctness pass and the capture pass.
    static cudaStream_t s2 = nullptr;
    static cudaEvent_t ev_fork = nullptr, ev_join = nullptr;
    if (s2 == nullptr) {
        cudaStreamCreateWithFlags(&s2, cudaStreamNonBlocking);
        cudaEventCreateWithFlags(&ev_fork, cudaEventDisableTiming);
        cudaEventCreateWithFlags(&ev_join, cudaEventDisableTiming);
    }

    // fork: record on the (captured) default stream, branch to s2
    cudaEventRecord(ev_fork, 0);
    cudaStreamWaitEvent(s2, ev_fork, 0);
    cvt_wo_kernel<<<(C_WO + 255) / 256, 256, 0, s2>>>(Wo);
    cudaEventRecord(ev_join, s2);

    // main stream: x + qkv weights, then the MMA chain
    cvt_main_kernel<<<(C_MAIN + 255) / 256, 256>>>(x, Wq, Wk, Wv);
    qkv_mma_kernel<<<dim3(18, 32), 256, GEMM_SMEM>>>(bq, bk, bv);
    attn_mma_kernel<<<dim3(SLEN / 128, NH, BDIM), 256, ATT_SMEM>>>();

    // join: oproj needs g_woh from the side stream
    cudaStreamWaitEvent(0, ev_join, 0);
    oproj_mma_kernel<<<dim3(16, 32), 256, GEMM_SMEM>>>(bo, out);
}

// round 15
// speedup vs baseline: 1.0805x; 1.0805x over previous
#include <cuda_runtime.h>
#include <cuda_fp16.h>
#include <math.h>
#include <stdint.h>

// Problem constants
#define BDIM   2
#define SLEN   2048
#define DMODEL 2048
#define NH     16
#define HD     128
#define MROWS  (BDIM * SLEN)   // 4096
#define NQKV   2304

// ---------------- scratch (no allocations allowed) ----------------
__device__ __half g_xh[(size_t)MROWS * DMODEL];
__device__ __half g_wh[(size_t)NQKV * DMODEL];   // [0,2048)=Wq [2048,2176)=Wk [2176,2304)=Wv
__device__ __half g_woh[(size_t)DMODEL * DMODEL];
__device__ __half g_qh[(size_t)MROWS * DMODEL];
__device__ __half g_kh[(size_t)MROWS * HD];
__device__ __half g_vth[(size_t)BDIM * HD * SLEN];   // [b][j][s]
__device__ __half g_ah[(size_t)MROWS * DMODEL];      // attn out, flat (b,h,s,hd)

// ---------------- helpers ----------------
__device__ __forceinline__ uint32_t smem_u32(const void* p) {
    uint32_t a;
    asm("{ .reg .u64 t; cvta.to.shared.u64 t, %1; cvt.u32.u64 %0, t; }" : "=r"(a) : "l"(p));
    return a;
}
#define CP16(dst, src) \
    asm volatile("cp.async.cg.shared.global [%0], [%1], 16;" :: "r"(dst), "l"(src) : "memory")
#define CPCOMMIT() asm volatile("cp.async.commit_group;" ::: "memory")
#define CPWAIT(n)  asm volatile("cp.async.wait_group %0;" :: "n"(n) : "memory")
#define LDSM4(r0, r1, r2, r3, addr) \
    asm volatile("ldmatrix.sync.aligned.m8n8.x4.shared.b16 {%0,%1,%2,%3},[%4];" \
        : "=r"(r0), "=r"(r1), "=r"(r2), "=r"(r3) : "r"(addr))

__device__ __forceinline__ void mma16816(float c[4],
    uint32_t a0, uint32_t a1, uint32_t a2, uint32_t a3, uint32_t b0, uint32_t b1)
{
    asm volatile(
        "mma.sync.aligned.m16n8k16.row.col.f32.f16.f16.f32 "
        "{%0,%1,%2,%3},{%4,%5,%6,%7},{%8,%9},{%0,%1,%2,%3};"
        : "+f"(c[0]), "+f"(c[1]), "+f"(c[2]), "+f"(c[3])
        : "r"(a0), "r"(a1), "r"(a2), "r"(a3), "r"(b0), "r"(b1));
}

// f16-accumulate variant
__device__ __forceinline__ void mma16816h(uint32_t c[2],
    uint32_t a0, uint32_t a1, uint32_t a2, uint32_t a3, uint32_t b0, uint32_t b1)
{
    asm volatile(
        "mma.sync.aligned.m16n8k16.row.col.f16.f16.f16.f16 "
        "{%0,%1},{%2,%3,%4,%5},{%6,%7},{%0,%1};"
        : "+r"(c[0]), "+r"(c[1])
        : "r"(a0), "r"(a1), "r"(a2), "r"(a3), "r"(b0), "r"(b1));
}

__device__ __forceinline__ uint32_t packh(float x, float y) {
    __half2 t = __floats2half2_rn(x, y);
    return reinterpret_cast<uint32_t&>(t);
}
__device__ __forceinline__ uint32_t ex2h2(uint32_t x) {
    uint32_t r;
    asm("ex2.approx.f16x2 %0, %1;" : "=r"(r) : "r"(x));
    return r;
}
__device__ __forceinline__ uint32_t hmul2(uint32_t a, uint32_t b) {
    __half2 r = __hmul2(reinterpret_cast<__half2&>(a), reinterpret_cast<__half2&>(b));
    return reinterpret_cast<uint32_t&>(r);
}
__device__ __forceinline__ uint32_t hadd2(uint32_t a, uint32_t b) {
    __half2 r = __hadd2(reinterpret_cast<__half2&>(a), reinterpret_cast<__half2&>(b));
    return reinterpret_cast<uint32_t&>(r);
}

// ---------------- fp32 -> fp16 conversions ----------------
#define C_X    2097152   // 4096*2048/4
#define C_WQ   1048576   // 2048*2048/4
#define C_WKV  65536     // 128*2048/4
#define C_MAIN (C_X + C_WQ + 2 * C_WKV)   // 3276800
#define C_WO   1048576

__global__ __launch_bounds__(256) void cvt_main_kernel(
    const float* __restrict__ x,  const float* __restrict__ Wq,
    const float* __restrict__ Wk, const float* __restrict__ Wv)
{
    int i = blockIdx.x * blockDim.x + threadIdx.x;
    if (i >= C_MAIN) return;
    const float* src; __half* dst; int off;
    if (i < C_X)                          { src = x;  dst = g_xh;  off = i; }
    else if (i < C_X + C_WQ)              { src = Wq; dst = g_wh;  off = i - C_X; }
    else if (i < C_X + C_WQ + C_WKV)      { src = Wk; dst = g_wh + (size_t)2048 * DMODEL; off = i - (C_X + C_WQ); }
    else                                  { src = Wv; dst = g_wh + (size_t)2176 * DMODEL; off = i - (C_X + C_WQ + C_WKV); }
    float4 v = ((const float4*)src)[off];
    uint2 H;
    H.x = packh(v.x, v.y);
    H.y = packh(v.z, v.w);
    ((uint2*)dst)[off] = H;
}

__global__ __launch_bounds__(256) void cvt_wo_kernel(const float* __restrict__ Wo)
{
    int i = blockIdx.x * blockDim.x + threadIdx.x;
    if (i >= C_WO) return;
    float4 v = ((const float4*)Wo)[i];
    uint2 H;
    H.x = packh(v.x, v.y);
    H.y = packh(v.z, v.w);
    ((uint2*)g_woh)[i] = H;
}

// ---------------- GEMM core: 128x128 block, K=2048, 3-stage pipeline ----------------
#define GSTR 72
#define GT   (128 * GSTR)          // 9216 elems per tensor tile
#define GSTAGE (2 * GT)            // A, B per stage
#define GNST 3
#define GEMM_SMEM (GNST * GSTAGE * 2)   // 110592 bytes
#define NCHUNK (DMODEL / 64)            // 32

__device__ __forceinline__ void gemm_core(
    const __half* __restrict__ A, const __half* __restrict__ B,
    float acc[2][8][4])
{
    extern __shared__ __align__(16) __half smg[];
    const uint32_t sb = smem_u32(smg);
    const int tid = threadIdx.x, lane = tid & 31, wid = tid >> 5;
    const int wm = wid & 3, wn = wid >> 2;

#pragma unroll
    for (int mt = 0; mt < 2; mt++)
#pragma unroll
        for (int nt = 0; nt < 8; nt++)
#pragma unroll
            for (int j = 0; j < 4; j++) acc[mt][nt][j] = 0.f;

    const int la = lane & 15, lb = lane >> 4;                 // A x4
    const int ln = (lane & 7) + ((lane >> 4) << 3);           // B x4 row
    const int lk = (lane >> 3) & 1;                           // B x4 k-half

    auto issue = [&](int c, int st) {
        const size_t k0 = (size_t)c * 64;
        const uint32_t dA = sb + (uint32_t)(st * GSTAGE) * 2;
        const uint32_t dB = dA + (uint32_t)GT * 2;
#pragma unroll
        for (int j = 0; j < 4; j++) {
            int idx = tid + j * 256;           // 0..1023
            int row = idx >> 3, slot = idx & 7;
            uint32_t doff = (uint32_t)(row * GSTR + slot * 8) * 2;
            size_t go = (size_t)row * DMODEL + k0 + slot * 8;
            CP16(dA + doff, A + go);
            CP16(dB + doff, B + go);
        }
        CPCOMMIT();
    };

    issue(0, 0);
    issue(1, 1);
    for (int c = 0; c < NCHUNK; c++) {
        const int st = c % GNST;
        if (c + 1 < NCHUNK) { CPWAIT(1); }
        else                { CPWAIT(0); }
        __syncthreads();
        if (c + 2 < NCHUNK) issue(c + 2, (c + 2) % GNST);

        const uint32_t A0 = sb + (uint32_t)(st * GSTAGE) * 2;
        const uint32_t B0 = A0 + (uint32_t)GT * 2;

#pragma unroll
        for (int ks = 0; ks < 4; ks++) {
            uint32_t aH[2][4];
#pragma unroll
            for (int mt = 0; mt < 2; mt++) {
                uint32_t ra = (uint32_t)((32 * wm + 16 * mt + la) * GSTR + ks * 16) * 2 + lb * 16;
                LDSM4(aH[mt][0], aH[mt][1], aH[mt][2], aH[mt][3], A0 + ra);
            }
#pragma unroll
            for (int ntp = 0; ntp < 4; ntp++) {
                uint32_t rb = (uint32_t)((64 * wn + 16 * ntp + ln) * GSTR + ks * 16) * 2 + lk * 16;
                uint32_t bh0, bh1, bh2, bh3;
                LDSM4(bh0, bh1, bh2, bh3, B0 + rb);
#pragma unroll
                for (int mt = 0; mt < 2; mt++) {
                    mma16816(acc[mt][2 * ntp],     aH[mt][0], aH[mt][1], aH[mt][2], aH[mt][3], bh0, bh1);
                    mma16816(acc[mt][2 * ntp + 1], aH[mt][0], aH[mt][1], aH[mt][2], aH[mt][3], bh2, bh3);
                }
            }
        }
    }
}

// ---------------- QKV projection (batch-split via bm0) ----------------
__global__ __launch_bounds__(256, 2) void qkv_mma_kernel(
    const float* __restrict__ bq, const float* __restrict__ bk, const float* __restrict__ bv,
    int bm0)
{
    const int bn = blockIdx.x;               // 0..17
    const int bm = blockIdx.y + bm0;         // bm0..bm0+15
    const int m0 = bm * 128;

    const __half* Bh;
    const float* bias;
    if (bn < 16)       { Bh = g_wh + (size_t)bn * 128 * DMODEL; bias = bq + bn * 128; }
    else if (bn == 16) { Bh = g_wh + (size_t)2048 * DMODEL;     bias = bk; }
    else               { Bh = g_wh + (size_t)2176 * DMODEL;     bias = bv; }

    float acc[2][8][4];
    gemm_core(g_xh + (size_t)m0 * DMODEL, Bh, acc);

    const int lane = threadIdx.x & 31, wid = threadIdx.x >> 5;
    const int wm = wid & 3, wn = wid >> 2;
    const int gr = lane >> 2, q4 = lane & 3;

#pragma unroll
    for (int mt = 0; mt < 2; mt++) {
#pragma unroll
        for (int nt = 0; nt < 8; nt++) {
            int rl = 32 * wm + 16 * mt + gr;
            int cl = 64 * wn + 8 * nt + 2 * q4;
            float bb0 = bias[cl], bb1 = bias[cl + 1];
#pragma unroll
            for (int hf = 0; hf < 2; hf++) {
                int r = rl + 8 * hf;
                float v0 = acc[mt][nt][2 * hf] + bb0;
                float v1 = acc[mt][nt][2 * hf + 1] + bb1;
                if (bn < 16) {
                    *(uint32_t*)&g_qh[(size_t)(m0 + r) * DMODEL + bn * 128 + cl] = packh(v0, v1);
                } else if (bn == 16) {
                    *(uint32_t*)&g_kh[(size_t)(m0 + r) * HD + cl] = packh(v0, v1);
                } else {
                    int mg = m0 + r;
                    int b = mg >> 11, s = mg & 2047;
                    size_t o0 = (size_t)b * HD * SLEN + (size_t)cl * SLEN + s;
                    g_vth[o0]        = __float2half_rn(v0);
                    g_vth[o0 + SLEN] = __float2half_rn(v1);
                }
            }
        }
    }
}

// ---------------- output projection (batch-split via bm0) ----------------
__global__ __launch_bounds__(256, 2) void oproj_mma_kernel(const float* __restrict__ bo,
                                                           float* __restrict__ out, int bm0)
{
    const int bn = blockIdx.x;               // 0..15
    const int bm = blockIdx.y + bm0;         // bm0..bm0+15
    const int m0 = bm * 128;
    const int n0 = bn * 128;

    float acc[2][8][4];
    gemm_core(g_ah + (size_t)m0 * DMODEL, g_woh + (size_t)n0 * DMODEL, acc);

    const int lane = threadIdx.x & 31, wid = threadIdx.x >> 5;
    const int wm = wid & 3, wn = wid >> 2;
    const int gr = lane >> 2, q4 = lane & 3;

#pragma unroll
    for (int mt = 0; mt < 2; mt++) {
#pragma unroll
        for (int nt = 0; nt < 8; nt++) {
            int rl = 32 * wm + 16 * mt + gr;
            int cl = 64 * wn + 8 * nt + 2 * q4;
            float bb0 = bo[n0 + cl], bb1 = bo[n0 + cl + 1];
#pragma unroll
            for (int hf = 0; hf < 2; hf++) {
                int r = rl + 8 * hf;
                float2 o2;
                o2.x = acc[mt][nt][2 * hf] + bb0;
                o2.y = acc[mt][nt][2 * hf + 1] + bb1;
                *(float2*)&out[(size_t)(m0 + r) * DMODEL + n0 + cl] = o2;
            }
        }
    }
}

// ---------------- attention (fp16 S-path; batch-split via param b) ----------------
#define QSTR 136
#define KSTR 136
#define VSTR 72
#define AQ_ELEMS (128 * QSTR)              // 17408
#define AK_ELEMS (64 * KSTR)               // 8704
#define AV_ELEMS (128 * VSTR)              // 9216
#define ASTAGE   (AK_ELEMS + AV_ELEMS)     // 17920 elems
#define OFF_ST   AQ_ELEMS
#define ATT_SMEM ((AQ_ELEMS + 2 * ASTAGE) * 2)   // 106496 bytes
#define NKT (SLEN / 64)                    // 32

__global__ __launch_bounds__(256, 2) void attn_mma_kernel(int b)
{
    extern __shared__ __align__(16) __half sm[];
    const uint32_t sb = smem_u32(sm);
    const int tid = threadIdx.x, lane = tid & 31, w = tid >> 5;
    const int qt = blockIdx.x, h = blockIdx.y;
    const int q0 = qt * 128;
    const int gr = lane >> 2, q4 = lane & 3;

    const __half* kbH = g_kh + (size_t)b * SLEN * HD;
    const __half* vbH = g_vth + (size_t)b * HD * SLEN;

    auto issue_kv = [&](int kt, int st) {
        const uint32_t stb = sb + (uint32_t)(OFF_ST + st * ASTAGE) * 2;
        const __half* kh = kbH + (size_t)kt * 64 * HD;
#pragma unroll
        for (int j = 0; j < 4; j++) {
            int idx = tid + j * 256;
            int row = idx >> 4, slot = idx & 15;
            CP16(stb + (uint32_t)(row * KSTR + slot * 8) * 2,
                 kh + (size_t)row * HD + slot * 8);
        }
        const __half* vh = vbH + (size_t)kt * 64;
#pragma unroll
        for (int j = 0; j < 4; j++) {
            int idx = tid + j * 256;
            int row = idx >> 3, slot = idx & 7;
            CP16(stb + (uint32_t)AK_ELEMS * 2 + (uint32_t)(row * VSTR + slot * 8) * 2,
                 vh + (size_t)row * SLEN + slot * 8);
        }
        CPCOMMIT();
    };

    // Q tile (128 x 128) via cp.async, issued first; lands with KV0 at iter-0 wait
    {
        const __half* qsH = g_qh + ((size_t)(b * SLEN + q0)) * DMODEL + h * HD;
#pragma unroll
        for (int it = 0; it < 8; it++) {
            int idx = tid + it * 256;
            int row = idx >> 4, slot = idx & 15;
            CP16(sb + (uint32_t)(row * QSTR + slot * 8) * 2,
                 qsH + (size_t)row * DMODEL + slot * 8);
        }
        CPCOMMIT();
    }
    issue_kv(0, 0);

    float oacc[16][4];
#pragma unroll
    for (int nt = 0; nt < 16; nt++)
#pragma unroll
        for (int j = 0; j < 4; j++) oacc[nt][j] = 0.f;

    float acc0 = 0.f, acc1 = 0.f;
    const uint32_t C2H = packh(0.12751744f, 0.12751744f);   // log2(e)/sqrt(128)
    const int qrow = 16 * w;

    const int la = lane & 15, lb = lane >> 4;
    const int ln = (lane & 7) + ((lane >> 4) << 3);
    const int lk = (lane >> 3) & 1;

    for (int kt = 0; kt < NKT; kt++) {
        const int st = kt & 1;
        CPWAIT(0);
        __syncthreads();
        if (kt + 1 < NKT) issue_kv(kt + 1, st ^ 1);   // overlaps all compute below

        const uint32_t stb = sb + (uint32_t)(OFF_ST + st * ASTAGE) * 2;
        const uint32_t KH0 = stb;
        const uint32_t VH0 = stb + (uint32_t)AK_ELEMS * 2;

        // S = Q @ K^T in f16-accumulate
        uint32_t sD[8][2];
#pragma unroll
        for (int nt = 0; nt < 8; nt++) { sD[nt][0] = 0u; sD[nt][1] = 0u; }

#pragma unroll
        for (int ks = 0; ks < 8; ks++) {
            uint32_t ra = (uint32_t)((qrow + la) * QSTR + ks * 16) * 2 + lb * 16;
            uint32_t aH0, aH1, aH2, aH3;
            LDSM4(aH0, aH1, aH2, aH3, sb + ra);
#pragma unroll
            for (int ntp = 0; ntp < 4; ntp++) {
                uint32_t rb = (uint32_t)((16 * ntp + ln) * KSTR + ks * 16) * 2 + lk * 16;
                uint32_t bh0, bh1, bh2, bh3;
                LDSM4(bh0, bh1, bh2, bh3, KH0 + rb);
                mma16816h(sD[2 * ntp],     aH0, aH1, aH2, aH3, bh0, bh1);
                mma16816h(sD[2 * ntp + 1], aH0, aH1, aH2, aH3, bh2, bh3);
            }
        }

        // exp interleaved with PV per kc-slice
        uint32_t d0 = 0u, d1 = 0u;
#pragma unroll
        for (int kc = 0; kc < 4; kc++) {
            uint32_t pa0 = ex2h2(hmul2(sD[2 * kc][0],     C2H));
            uint32_t pa1 = ex2h2(hmul2(sD[2 * kc][1],     C2H));
            uint32_t pb0 = ex2h2(hmul2(sD[2 * kc + 1][0], C2H));
            uint32_t pb1 = ex2h2(hmul2(sD[2 * kc + 1][1], C2H));
            d0 = hadd2(d0, hadd2(pa0, pb0));
            d1 = hadd2(d1, hadd2(pa1, pb1));
#pragma unroll
            for (int ntp = 0; ntp < 8; ntp++) {
                uint32_t rb = (uint32_t)((16 * ntp + ln) * VSTR + kc * 16) * 2 + lk * 16;
                uint32_t bh0, bh1, bh2, bh3;
                LDSM4(bh0, bh1, bh2, bh3, VH0 + rb);
                mma16816(oacc[2 * ntp],     pa0, pa1, pb0, pb1, bh0, bh1);
                mma16816(oacc[2 * ntp + 1], pa0, pa1, pb0, pb1, bh2, bh3);
            }
        }
        {
            float2 f0 = __half22float2(reinterpret_cast<__half2&>(d0));
            float2 f1 = __half22float2(reinterpret_cast<__half2&>(d1));
            acc0 += f0.x + f0.y;
            acc1 += f1.x + f1.y;
        }
    }

    // final denominator reduction across the quad (lanes sharing a row)
    acc0 += __shfl_xor_sync(0xffffffffu, acc0, 1);
    acc0 += __shfl_xor_sync(0xffffffffu, acc0, 2);
    acc1 += __shfl_xor_sync(0xffffffffu, acc1, 1);
    acc1 += __shfl_xor_sync(0xffffffffu, acc1, 2);
    float i0 = 1.f / acc0, i1 = 1.f / acc1;

    // normalize + write fp16 to flat (b,h,s,hd)
    size_t rg = (size_t)((b * NH + h) * SLEN + q0 + qrow + gr);
#pragma unroll
    for (int nt = 0; nt < 16; nt++) {
        int col = 8 * nt + 2 * q4;
        *(uint32_t*)&g_ah[rg * HD + col]       = packh(oacc[nt][0] * i0, oacc[nt][1] * i0);
        *(uint32_t*)&g_ah[(rg + 8) * HD + col] = packh(oacc[nt][2] * i1, oacc[nt][3] * i1);
    }
}

// ---------------- launch: two batch-pipelined dependency chains ----------------
extern "C" void kernel_launch(void* const* d_in, const int* in_sizes, int n_in,
                              void* d_out, int out_size)
{
    const float* x  = (const float*)d_in[0];
    const float* Wq = (const float*)d_in[1];
    const float* bq = (const float*)d_in[2];
    const float* Wk = (const float*)d_in[3];
    const float* bk = (const float*)d_in[4];
    const float* Wv = (const float*)d_in[5];
    const float* bv = (const float*)d_in[6];
    const float* Wo = (const float*)d_in[7];
    const float* bo = (const float*)d_in[8];
    float* out = (float*)d_out;

    cudaFuncSetAttribute(qkv_mma_kernel,   cudaFuncAttributeMaxDynamicSharedMemorySize, GEMM_SMEM);
    cudaFuncSetAttribute(oproj_mma_kernel, cudaFuncAttributeMaxDynamicSharedMemorySize, GEMM_SMEM);
    cudaFuncSetAttribute(attn_mma_kernel,  cudaFuncAttributeMaxDynamicSharedMemorySize, ATT_SMEM);

    static cudaStream_t s2 = nullptr;
    static cudaEvent_t ev_fork = nullptr, ev_cvt = nullptr, ev_wo = nullptr, ev_done = nullptr;
    if (s2 == nullptr) {
        cudaStreamCreateWithFlags(&s2, cudaStreamNonBlocking);
        cudaEventCreateWithFlags(&ev_fork, cudaEventDisableTiming);
        cudaEventCreateWithFlags(&ev_cvt,  cudaEventDisableTiming);
        cudaEventCreateWithFlags(&ev_wo,   cudaEventDisableTiming);
        cudaEventCreateWithFlags(&ev_done, cudaEventDisableTiming);
    }

    // fork s2 off the capture stream
    cudaEventRecord(ev_fork, 0);
    cudaStreamWaitEvent(s2, ev_fork, 0);

    // s2: Wo conversion first (independent), then the batch-1 chain
    cvt_wo_kernel<<<(C_WO + 255) / 256, 256, 0, s2>>>(Wo);
    cudaEventRecord(ev_wo, s2);

    // s1 (capture stream): conversions for x + qkv weights
    cvt_main_kernel<<<(C_MAIN + 255) / 256, 256>>>(x, Wq, Wk, Wv);
    cudaEventRecord(ev_cvt, 0);

    // batch-0 chain on s1
    qkv_mma_kernel<<<dim3(18, 16), 256, GEMM_SMEM>>>(bq, bk, bv, 0);
    attn_mma_kernel<<<dim3(SLEN / 128, NH, 1), 256, ATT_SMEM>>>(0);

    // batch-1 chain on s2 (waits only on cvt_main)
    cudaStreamWaitEvent(s2, ev_cvt, 0);
    qkv_mma_kernel<<<dim3(18, 16), 256, GEMM_SMEM, s2>>>(bq, bk, bv, 16);
    attn_mma_kernel<<<dim3(SLEN / 128, NH, 1), 256, ATT_SMEM, s2>>>(1);
    oproj_mma_kernel<<<dim3(16, 16), 256, GEMM_SMEM, s2>>>(bo, out, 16);   // rows 2048..4095 (needs g_woh: after cvt_wo on s2)
    cudaEventRecord(ev_done, s2);

    // batch-0 oproj on s1 (needs g_woh from s2's cvt_wo)
    cudaStreamWaitEvent(0, ev_wo, 0);
    oproj_mma_kernel<<<dim3(16, 16), 256, GEMM_SMEM>>>(bo, out, 0);        // rows 0..2047

    // join: capture stream must see the s2 chain complete
    cudaStreamWaitEvent(0, ev_done, 0);
}

// round 16
// speedup vs baseline: 1.0817x; 1.0011x over previous
#include <cuda_runtime.h>
#include <cuda_fp16.h>
#include <math.h>
#include <stdint.h>

// Problem constants
#define BDIM   2
#define SLEN   2048
#define DMODEL 2048
#define NH     16
#define HD     128
#define MROWS  (BDIM * SLEN)   // 4096
#define NQKV   2304

// ---------------- scratch (no allocations allowed) ----------------
__device__ __half g_xh[(size_t)MROWS * DMODEL];
__device__ __half g_wh[(size_t)NQKV * DMODEL];   // [0,2048)=Wq [2048,2176)=Wk [2176,2304)=Wv
__device__ __half g_woh[(size_t)DMODEL * DMODEL];
__device__ __half g_qh[(size_t)MROWS * DMODEL];
__device__ __half g_kh[(size_t)MROWS * HD];
__device__ __half g_vth[(size_t)BDIM * HD * SLEN];   // [b][j][s]
__device__ __half g_ah[(size_t)MROWS * DMODEL];      // attn out, flat (b,h,s,hd)

// ---------------- helpers ----------------
__device__ __forceinline__ uint32_t smem_u32(const void* p) {
    uint32_t a;
    asm("{ .reg .u64 t; cvta.to.shared.u64 t, %1; cvt.u32.u64 %0, t; }" : "=r"(a) : "l"(p));
    return a;
}
#define CP16(dst, src) \
    asm volatile("cp.async.cg.shared.global [%0], [%1], 16;" :: "r"(dst), "l"(src) : "memory")
#define CPCOMMIT() asm volatile("cp.async.commit_group;" ::: "memory")
#define CPWAIT(n)  asm volatile("cp.async.wait_group %0;" :: "n"(n) : "memory")
#define LDSM4(r0, r1, r2, r3, addr) \
    asm volatile("ldmatrix.sync.aligned.m8n8.x4.shared.b16 {%0,%1,%2,%3},[%4];" \
        : "=r"(r0), "=r"(r1), "=r"(r2), "=r"(r3) : "r"(addr))

__device__ __forceinline__ void mma16816(float c[4],
    uint32_t a0, uint32_t a1, uint32_t a2, uint32_t a3, uint32_t b0, uint32_t b1)
{
    asm volatile(
        "mma.sync.aligned.m16n8k16.row.col.f32.f16.f16.f32 "
        "{%0,%1,%2,%3},{%4,%5,%6,%7},{%8,%9},{%0,%1,%2,%3};"
        : "+f"(c[0]), "+f"(c[1]), "+f"(c[2]), "+f"(c[3])
        : "r"(a0), "r"(a1), "r"(a2), "r"(a3), "r"(b0), "r"(b1));
}

// f16-accumulate variant
__device__ __forceinline__ void mma16816h(uint32_t c[2],
    uint32_t a0, uint32_t a1, uint32_t a2, uint32_t a3, uint32_t b0, uint32_t b1)
{
    asm volatile(
        "mma.sync.aligned.m16n8k16.row.col.f16.f16.f16.f16 "
        "{%0,%1},{%2,%3,%4,%5},{%6,%7},{%0,%1};"
        : "+r"(c[0]), "+r"(c[1])
        : "r"(a0), "r"(a1), "r"(a2), "r"(a3), "r"(b0), "r"(b1));
}

__device__ __forceinline__ uint32_t packh(float x, float y) {
    __half2 t = __floats2half2_rn(x, y);
    return reinterpret_cast<uint32_t&>(t);
}
__device__ __forceinline__ uint32_t ex2h2(uint32_t x) {
    uint32_t r;
    asm("ex2.approx.f16x2 %0, %1;" : "=r"(r) : "r"(x));
    return r;
}
__device__ __forceinline__ uint32_t hmul2(uint32_t a, uint32_t b) {
    __half2 r = __hmul2(reinterpret_cast<__half2&>(a), reinterpret_cast<__half2&>(b));
    return reinterpret_cast<uint32_t&>(r);
}
__device__ __forceinline__ uint32_t hadd2(uint32_t a, uint32_t b) {
    __half2 r = __hadd2(reinterpret_cast<__half2&>(a), reinterpret_cast<__half2&>(b));
    return reinterpret_cast<uint32_t&>(r);
}

// ---------------- fp32 -> fp16 conversions ----------------
#define C_X    2097152   // 4096*2048/4
#define C_WQ   1048576   // 2048*2048/4
#define C_WKV  65536     // 128*2048/4
#define C_MAIN (C_X + C_WQ + 2 * C_WKV)   // 3276800
#define C_WO   1048576

__global__ __launch_bounds__(256) void cvt_main_kernel(
    const float* __restrict__ x,  const float* __restrict__ Wq,
    const float* __restrict__ Wk, const float* __restrict__ Wv)
{
    int i = blockIdx.x * blockDim.x + threadIdx.x;
    if (i >= C_MAIN) return;
    const float* src; __half* dst; int off;
    if (i < C_X)                          { src = x;  dst = g_xh;  off = i; }
    else if (i < C_X + C_WQ)              { src = Wq; dst = g_wh;  off = i - C_X; }
    else if (i < C_X + C_WQ + C_WKV)      { src = Wk; dst = g_wh + (size_t)2048 * DMODEL; off = i - (C_X + C_WQ); }
    else                                  { src = Wv; dst = g_wh + (size_t)2176 * DMODEL; off = i - (C_X + C_WQ + C_WKV); }
    float4 v = ((const float4*)src)[off];
    uint2 H;
    H.x = packh(v.x, v.y);
    H.y = packh(v.z, v.w);
    ((uint2*)dst)[off] = H;
}

__global__ __launch_bounds__(256) void cvt_wo_kernel(const float* __restrict__ Wo)
{
    int i = blockIdx.x * blockDim.x + threadIdx.x;
    if (i >= C_WO) return;
    float4 v = ((const float4*)Wo)[i];
    uint2 H;
    H.x = packh(v.x, v.y);
    H.y = packh(v.z, v.w);
    ((uint2*)g_woh)[i] = H;
}

// ---------------- GEMM core: 128x128 block, K=2048, 3-stage pipeline ----------------
#define GSTR 72
#define GT   (128 * GSTR)          // 9216 elems per tensor tile
#define GSTAGE (2 * GT)            // A, B per stage
#define GNST 3
#define GEMM_SMEM (GNST * GSTAGE * 2)   // 110592 bytes
#define NCHUNK (DMODEL / 64)            // 32

__device__ __forceinline__ void gemm_core(
    const __half* __restrict__ A, const __half* __restrict__ B,
    float acc[2][8][4])
{
    extern __shared__ __align__(16) __half smg[];
    const uint32_t sb = smem_u32(smg);
    const int tid = threadIdx.x, lane = tid & 31, wid = tid >> 5;
    const int wm = wid & 3, wn = wid >> 2;

#pragma unroll
    for (int mt = 0; mt < 2; mt++)
#pragma unroll
        for (int nt = 0; nt < 8; nt++)
#pragma unroll
            for (int j = 0; j < 4; j++) acc[mt][nt][j] = 0.f;

    const int la = lane & 15, lb = lane >> 4;                 // A x4
    const int ln = (lane & 7) + ((lane >> 4) << 3);           // B x4 row
    const int lk = (lane >> 3) & 1;                           // B x4 k-half

    auto issue = [&](int c, int st) {
        const size_t k0 = (size_t)c * 64;
        const uint32_t dA = sb + (uint32_t)(st * GSTAGE) * 2;
        const uint32_t dB = dA + (uint32_t)GT * 2;
#pragma unroll
        for (int j = 0; j < 4; j++) {
            int idx = tid + j * 256;           // 0..1023
            int row = idx >> 3, slot = idx & 7;
            uint32_t doff = (uint32_t)(row * GSTR + slot * 8) * 2;
            size_t go = (size_t)row * DMODEL + k0 + slot * 8;
            CP16(dA + doff, A + go);
            CP16(dB + doff, B + go);
        }
        CPCOMMIT();
    };

    issue(0, 0);
    issue(1, 1);
    for (int c = 0; c < NCHUNK; c++) {
        const int st = c % GNST;
        if (c + 1 < NCHUNK) { CPWAIT(1); }
        else                { CPWAIT(0); }
        __syncthreads();
        if (c + 2 < NCHUNK) issue(c + 2, (c + 2) % GNST);

        const uint32_t A0 = sb + (uint32_t)(st * GSTAGE) * 2;
        const uint32_t B0 = A0 + (uint32_t)GT * 2;

#pragma unroll
        for (int ks = 0; ks < 4; ks++) {
            uint32_t aH[2][4];
#pragma unroll
            for (int mt = 0; mt < 2; mt++) {
                uint32_t ra = (uint32_t)((32 * wm + 16 * mt + la) * GSTR + ks * 16) * 2 + lb * 16;
                LDSM4(aH[mt][0], aH[mt][1], aH[mt][2], aH[mt][3], A0 + ra);
            }
#pragma unroll
            for (int ntp = 0; ntp < 4; ntp++) {
                uint32_t rb = (uint32_t)((64 * wn + 16 * ntp + ln) * GSTR + ks * 16) * 2 + lk * 16;
                uint32_t bh0, bh1, bh2, bh3;
                LDSM4(bh0, bh1, bh2, bh3, B0 + rb);
#pragma unroll
                for (int mt = 0; mt < 2; mt++) {
                    mma16816(acc[mt][2 * ntp],     aH[mt][0], aH[mt][1], aH[mt][2], aH[mt][3], bh0, bh1);
                    mma16816(acc[mt][2 * ntp + 1], aH[mt][0], aH[mt][1], aH[mt][2], aH[mt][3], bh2, bh3);
                }
            }
        }
    }
}

// ---------------- QKV projection (batch-split via bm0) ----------------
__global__ __launch_bounds__(256, 2) void qkv_mma_kernel(
    const float* __restrict__ bq, const float* __restrict__ bk, const float* __restrict__ bv,
    int bm0)
{
    const int bn = blockIdx.x;               // 0..17
    const int bm = blockIdx.y + bm0;         // bm0..bm0+15
    const int m0 = bm * 128;

    const __half* Bh;
    const float* bias;
    if (bn < 16)       { Bh = g_wh + (size_t)bn * 128 * DMODEL; bias = bq + bn * 128; }
    else if (bn == 16) { Bh = g_wh + (size_t)2048 * DMODEL;     bias = bk; }
    else               { Bh = g_wh + (size_t)2176 * DMODEL;     bias = bv; }

    float acc[2][8][4];
    gemm_core(g_xh + (size_t)m0 * DMODEL, Bh, acc);

    const int lane = threadIdx.x & 31, wid = threadIdx.x >> 5;
    const int wm = wid & 3, wn = wid >> 2;
    const int gr = lane >> 2, q4 = lane & 3;

#pragma unroll
    for (int mt = 0; mt < 2; mt++) {
#pragma unroll
        for (int nt = 0; nt < 8; nt++) {
            int rl = 32 * wm + 16 * mt + gr;
            int cl = 64 * wn + 8 * nt + 2 * q4;
            float bb0 = bias[cl], bb1 = bias[cl + 1];
#pragma unroll
            for (int hf = 0; hf < 2; hf++) {
                int r = rl + 8 * hf;
                float v0 = acc[mt][nt][2 * hf] + bb0;
                float v1 = acc[mt][nt][2 * hf + 1] + bb1;
                if (bn < 16) {
                    *(uint32_t*)&g_qh[(size_t)(m0 + r) * DMODEL + bn * 128 + cl] = packh(v0, v1);
                } else if (bn == 16) {
                    *(uint32_t*)&g_kh[(size_t)(m0 + r) * HD + cl] = packh(v0, v1);
                } else {
                    int mg = m0 + r;
                    int b = mg >> 11, s = mg & 2047;
                    size_t o0 = (size_t)b * HD * SLEN + (size_t)cl * SLEN + s;
                    g_vth[o0]        = __float2half_rn(v0);
                    g_vth[o0 + SLEN] = __float2half_rn(v1);
                }
            }
        }
    }
}

// ---------------- output projection (bm-range split) ----------------
__global__ __launch_bounds__(256, 2) void oproj_mma_kernel(const float* __restrict__ bo,
                                                           float* __restrict__ out, int bm0)
{
    const int bn = blockIdx.x;               // 0..15
    const int bm = blockIdx.y + bm0;         // bm0..bm0+7
    const int m0 = bm * 128;
    const int n0 = bn * 128;

    float acc[2][8][4];
    gemm_core(g_ah + (size_t)m0 * DMODEL, g_woh + (size_t)n0 * DMODEL, acc);

    const int lane = threadIdx.x & 31, wid = threadIdx.x >> 5;
    const int wm = wid & 3, wn = wid >> 2;
    const int gr = lane >> 2, q4 = lane & 3;

#pragma unroll
    for (int mt = 0; mt < 2; mt++) {
#pragma unroll
        for (int nt = 0; nt < 8; nt++) {
            int rl = 32 * wm + 16 * mt + gr;
            int cl = 64 * wn + 8 * nt + 2 * q4;
            float bb0 = bo[n0 + cl], bb1 = bo[n0 + cl + 1];
#pragma unroll
            for (int hf = 0; hf < 2; hf++) {
                int r = rl + 8 * hf;
                float2 o2;
                o2.x = acc[mt][nt][2 * hf] + bb0;
                o2.y = acc[mt][nt][2 * hf + 1] + bb1;
                *(float2*)&out[(size_t)(m0 + r) * DMODEL + n0 + cl] = o2;
            }
        }
    }
}

// ---------------- attention (fp16 S-path; batch + head-half split) ----------------
#define QSTR 136
#define KSTR 136
#define VSTR 72
#define AQ_ELEMS (128 * QSTR)              // 17408
#define AK_ELEMS (64 * KSTR)               // 8704
#define AV_ELEMS (128 * VSTR)              // 9216
#define ASTAGE   (AK_ELEMS + AV_ELEMS)     // 17920 elems
#define OFF_ST   AQ_ELEMS
#define ATT_SMEM ((AQ_ELEMS + 2 * ASTAGE) * 2)   // 106496 bytes
#define NKT (SLEN / 64)                    // 32

__global__ __launch_bounds__(256, 2) void attn_mma_kernel(int b, int h0)
{
    extern __shared__ __align__(16) __half sm[];
    const uint32_t sb = smem_u32(sm);
    const int tid = threadIdx.x, lane = tid & 31, w = tid >> 5;
    const int qt = blockIdx.x, h = blockIdx.y + h0;
    const int q0 = qt * 128;
    const int gr = lane >> 2, q4 = lane & 3;

    const __half* kbH = g_kh + (size_t)b * SLEN * HD;
    const __half* vbH = g_vth + (size_t)b * HD * SLEN;

    auto issue_kv = [&](int kt, int st) {
        const uint32_t stb = sb + (uint32_t)(OFF_ST + st * ASTAGE) * 2;
        const __half* kh = kbH + (size_t)kt * 64 * HD;
#pragma unroll
        for (int j = 0; j < 4; j++) {
            int idx = tid + j * 256;
            int row = idx >> 4, slot = idx & 15;
            CP16(stb + (uint32_t)(row * KSTR + slot * 8) * 2,
                 kh + (size_t)row * HD + slot * 8);
        }
        const __half* vh = vbH + (size_t)kt * 64;
#pragma unroll
        for (int j = 0; j < 4; j++) {
            int idx = tid + j * 256;
            int row = idx >> 3, slot = idx & 7;
            CP16(stb + (uint32_t)AK_ELEMS * 2 + (uint32_t)(row * VSTR + slot * 8) * 2,
                 vh + (size_t)row * SLEN + slot * 8);
        }
        CPCOMMIT();
    };

    // Q tile (128 x 128) via cp.async, issued first; lands with KV0 at iter-0 wait
    {
        const __half* qsH = g_qh + ((size_t)(b * SLEN + q0)) * DMODEL + h * HD;
#pragma unroll
        for (int it = 0; it < 8; it++) {
            int idx = tid + it * 256;
            int row = idx >> 4, slot = idx & 15;
            CP16(sb + (uint32_t)(row * QSTR + slot * 8) * 2,
                 qsH + (size_t)row * DMODEL + slot * 8);
        }
        CPCOMMIT();
    }
    issue_kv(0, 0);

    float oacc[16][4];
#pragma unroll
    for (int nt = 0; nt < 16; nt++)
#pragma unroll
        for (int j = 0; j < 4; j++) oacc[nt][j] = 0.f;

    float acc0 = 0.f, acc1 = 0.f;
    const uint32_t C2H = packh(0.12751744f, 0.12751744f);   // log2(e)/sqrt(128)
    const int qrow = 16 * w;

    const int la = lane & 15, lb = lane >> 4;
    const int ln = (lane & 7) + ((lane >> 4) << 3);
    const int lk = (lane >> 3) & 1;

    for (int kt = 0; kt < NKT; kt++) {
        const int st = kt & 1;
        CPWAIT(0);
        __syncthreads();
        if (kt + 1 < NKT) issue_kv(kt + 1, st ^ 1);   // overlaps all compute below

        const uint32_t stb = sb + (uint32_t)(OFF_ST + st * ASTAGE) * 2;
        const uint32_t KH0 = stb;
        const uint32_t VH0 = stb + (uint32_t)AK_ELEMS * 2;

        // S = Q @ K^T in f16-accumulate
        uint32_t sD[8][2];
#pragma unroll
        for (int nt = 0; nt < 8; nt++) { sD[nt][0] = 0u; sD[nt][1] = 0u; }

#pragma unroll
        for (int ks = 0; ks < 8; ks++) {
            uint32_t ra = (uint32_t)((qrow + la) * QSTR + ks * 16) * 2 + lb * 16;
            uint32_t aH0, aH1, aH2, aH3;
            LDSM4(aH0, aH1, aH2, aH3, sb + ra);
#pragma unroll
            for (int ntp = 0; ntp < 4; ntp++) {
                uint32_t rb = (uint32_t)((16 * ntp + ln) * KSTR + ks * 16) * 2 + lk * 16;
                uint32_t bh0, bh1, bh2, bh3;
                LDSM4(bh0, bh1, bh2, bh3, KH0 + rb);
                mma16816h(sD[2 * ntp],     aH0, aH1, aH2, aH3, bh0, bh1);
                mma16816h(sD[2 * ntp + 1], aH0, aH1, aH2, aH3, bh2, bh3);
            }
        }

        // exp interleaved with PV per kc-slice
        uint32_t d0 = 0u, d1 = 0u;
#pragma unroll
        for (int kc = 0; kc < 4; kc++) {
            uint32_t pa0 = ex2h2(hmul2(sD[2 * kc][0],     C2H));
            uint32_t pa1 = ex2h2(hmul2(sD[2 * kc][1],     C2H));
            uint32_t pb0 = ex2h2(hmul2(sD[2 * kc + 1][0], C2H));
            uint32_t pb1 = ex2h2(hmul2(sD[2 * kc + 1][1], C2H));
            d0 = hadd2(d0, hadd2(pa0, pb0));
            d1 = hadd2(d1, hadd2(pa1, pb1));
#pragma unroll
            for (int ntp = 0; ntp < 8; ntp++) {
                uint32_t rb = (uint32_t)((16 * ntp + ln) * VSTR + kc * 16) * 2 + lk * 16;
                uint32_t bh0, bh1, bh2, bh3;
                LDSM4(bh0, bh1, bh2, bh3, VH0 + rb);
                mma16816(oacc[2 * ntp],     pa0, pa1, pb0, pb1, bh0, bh1);
                mma16816(oacc[2 * ntp + 1], pa0, pa1, pb0, pb1, bh2, bh3);
            }
        }
        {
            float2 f0 = __half22float2(reinterpret_cast<__half2&>(d0));
            float2 f1 = __half22float2(reinterpret_cast<__half2&>(d1));
            acc0 += f0.x + f0.y;
            acc1 += f1.x + f1.y;
        }
    }

    // final denominator reduction across the quad (lanes sharing a row)
    acc0 += __shfl_xor_sync(0xffffffffu, acc0, 1);
    acc0 += __shfl_xor_sync(0xffffffffu, acc0, 2);
    acc1 += __shfl_xor_sync(0xffffffffu, acc1, 1);
    acc1 += __shfl_xor_sync(0xffffffffu, acc1, 2);
    float i0 = 1.f / acc0, i1 = 1.f / acc1;

    // normalize + write fp16 to flat (b,h,s,hd)
    size_t rg = (size_t)((b * NH + h) * SLEN + q0 + qrow + gr);
#pragma unroll
    for (int nt = 0; nt < 16; nt++) {
        int col = 8 * nt + 2 * q4;
        *(uint32_t*)&g_ah[rg * HD + col]       = packh(oacc[nt][0] * i0, oacc[nt][1] * i0);
        *(uint32_t*)&g_ah[(rg + 8) * HD + col] = packh(oacc[nt][2] * i1, oacc[nt][3] * i1);
    }
}

// ---------------- launch: 4-stream head-half pipeline ----------------
// oproj bm maps to a single head: bm = b*16 + h. So each oproj quarter depends
// only on the matching attention head-half.
extern "C" void kernel_launch(void* const* d_in, const int* in_sizes, int n_in,
                              void* d_out, int out_size)
{
    const float* x  = (const float*)d_in[0];
    const float* Wq = (const float*)d_in[1];
    const float* bq = (const float*)d_in[2];
    const float* Wk = (const float*)d_in[3];
    const float* bk = (const float*)d_in[4];
    const float* Wv = (const float*)d_in[5];
    const float* bv = (const float*)d_in[6];
    const float* Wo = (const float*)d_in[7];
    const float* bo = (const float*)d_in[8];
    float* out = (float*)d_out;

    cudaFuncSetAttribute(qkv_mma_kernel,   cudaFuncAttributeMaxDynamicSharedMemorySize, GEMM_SMEM);
    cudaFuncSetAttribute(oproj_mma_kernel, cudaFuncAttributeMaxDynamicSharedMemorySize, GEMM_SMEM);
    cudaFuncSetAttribute(attn_mma_kernel,  cudaFuncAttributeMaxDynamicSharedMemorySize, ATT_SMEM);

    static cudaStream_t s2 = nullptr, s3 = nullptr, s4 = nullptr;
    static cudaEvent_t ev_fork = nullptr, ev_cvt = nullptr, ev_wo = nullptr;
    static cudaEvent_t ev_qkv0 = nullptr, ev_qkv1 = nullptr;
    static cudaEvent_t ev_d2 = nullptr, ev_d3 = nullptr, ev_d4 = nullptr;
    if (s2 == nullptr) {
        cudaStreamCreateWithFlags(&s2, cudaStreamNonBlocking);
        cudaStreamCreateWithFlags(&s3, cudaStreamNonBlocking);
        cudaStreamCreateWithFlags(&s4, cudaStreamNonBlocking);
        cudaEventCreateWithFlags(&ev_fork, cudaEventDisableTiming);
        cudaEventCreateWithFlags(&ev_cvt,  cudaEventDisableTiming);
        cudaEventCreateWithFlags(&ev_wo,   cudaEventDisableTiming);
        cudaEventCreateWithFlags(&ev_qkv0, cudaEventDisableTiming);
        cudaEventCreateWithFlags(&ev_qkv1, cudaEventDisableTiming);
        cudaEventCreateWithFlags(&ev_d2,   cudaEventDisableTiming);
        cudaEventCreateWithFlags(&ev_d3,   cudaEventDisableTiming);
        cudaEventCreateWithFlags(&ev_d4,   cudaEventDisableTiming);
    }

    // fork all side streams off the capture stream
    cudaEventRecord(ev_fork, 0);
    cudaStreamWaitEvent(s2, ev_fork, 0);
    cudaStreamWaitEvent(s3, ev_fork, 0);
    cudaStreamWaitEvent(s4, ev_fork, 0);

    // s2: Wo conversion (independent of everything)
    cvt_wo_kernel<<<(C_WO + 255) / 256, 256, 0, s2>>>(Wo);
    cudaEventRecord(ev_wo, s2);

    // s1: conversions for x + qkv weights
    cvt_main_kernel<<<(C_MAIN + 255) / 256, 256>>>(x, Wq, Wk, Wv);
    cudaEventRecord(ev_cvt, 0);

    // s1: batch-0 qkv
    qkv_mma_kernel<<<dim3(18, 16), 256, GEMM_SMEM>>>(bq, bk, bv, 0);
    cudaEventRecord(ev_qkv0, 0);

    // s2: batch-1 qkv (after cvt_main)
    cudaStreamWaitEvent(s2, ev_cvt, 0);
    qkv_mma_kernel<<<dim3(18, 16), 256, GEMM_SMEM, s2>>>(bq, bk, bv, 16);
    cudaEventRecord(ev_qkv1, s2);

    // s1: attn(b0, h0-7) -> oproj(bm 0-7)
    attn_mma_kernel<<<dim3(16, 8, 1), 256, ATT_SMEM>>>(0, 0);
    cudaStreamWaitEvent(0, ev_wo, 0);
    oproj_mma_kernel<<<dim3(16, 8), 256, GEMM_SMEM>>>(bo, out, 0);

    // s3: attn(b0, h8-15) -> oproj(bm 8-15)
    cudaStreamWaitEvent(s3, ev_qkv0, 0);
    attn_mma_kernel<<<dim3(16, 8, 1), 256, ATT_SMEM, s3>>>(0, 8);
    cudaStreamWaitEvent(s3, ev_wo, 0);
    oproj_mma_kernel<<<dim3(16, 8), 256, GEMM_SMEM, s3>>>(bo, out, 8);
    cudaEventRecord(ev_d3, s3);

    // s2: attn(b1, h0-7) -> oproj(bm 16-23)   (ev_wo already in-stream on s2)
    attn_mma_kernel<<<dim3(16, 8, 1), 256, ATT_SMEM, s2>>>(1, 0);
    oproj_mma_kernel<<<dim3(16, 8), 256, GEMM_SMEM, s2>>>(bo, out, 16);
    cudaEventRecord(ev_d2, s2);

    // s4: attn(b1, h8-15) -> oproj(bm 24-31)
    cudaStreamWaitEvent(s4, ev_qkv1, 0);
    attn_mma_kernel<<<dim3(16, 8, 1), 256, ATT_SMEM, s4>>>(1, 8);
    cudaStreamWaitEvent(s4, ev_wo, 0);
    oproj_mma_kernel<<<dim3(16, 8), 256, GEMM_SMEM, s4>>>(bo, out, 24);
    cudaEventRecord(ev_d4, s4);

    // join: capture stream waits for all side chains
    cudaStreamWaitEvent(0, ev_d2, 0);
    cudaStreamWaitEvent(0, ev_d3, 0);
    cudaStreamWaitEvent(0, ev_d4, 0);
}